// round 14
// baseline (speedup 1.0000x reference)
#include <cuda_runtime.h>
#include <math.h>

// Problem constants
#define NCHUNK 32
#define NBATCH 64
#define HALF   128
#define SIZE   (2 * HALF)            // 256
#define NROWS  (NCHUNK * NBATCH)     // 2048
#define C_SCALE 1e-4f
#define M_SCALE 1e-5f

#define YDOT_FLOATS (NROWS * SIZE)   // 524288

// Measured-best geometry: 16 segments x 128 groups = 2048 blocks.
// Each block holds one 16KB segment (4 float4/thread in registers) and
// writes it to 16 CONTIGUOUS batch copies with unroll-4 streaming STG.128.
// R14 delta: J broadcast issues FIRST; ydot (y-load latency + compute)
// hides under the store drain instead of delaying the store stream.
#define SEGS 16
#define GRP  128
#define NBLK (SEGS * GRP)            // 2048
#define CPB  (NROWS / GRP)           // 16 copies per block
#define SEG_F4 1024                  // float4 per segment

// ---------------------------------------------------------------------------
// Closed-form Jb[r][c] (256x256)
// ---------------------------------------------------------------------------
__device__ __forceinline__ float jb_val(int r, int c,
                                        const float* __restrict__ K,
                                        const float* __restrict__ C,
                                        const float* __restrict__ M) {
    if (r < HALF) {
        return (c == r + HALF) ? 1.0f : 0.0f;
    }
    int i = r - HALF;
    int j = (c < HALF) ? c : (c - HALF);
    int d = j - i;
    if (d < -1 || d > 1) return 0.0f;

    float Mi = M[i] * M_SCALE;
    if (c < HALF) {
        if (d == 0) {
            float v = -K[i] / Mi;
            if (i > 0) v -= K[i - 1] / Mi;
            return v;
        } else if (d == 1) {
            return K[i] / Mi;
        } else {
            return K[i - 1] / Mi;
        }
    } else {
        if (d == 0) {
            float v = -(C[i] * C_SCALE) / Mi;
            if (i > 0) v -= (C[i - 1] * C_SCALE) / Mi;
            return v;
        } else if (d == 1) {
            return (C[i] * C_SCALE) / Mi;
        } else {
            return (C[i - 1] * C_SCALE) / Mi;
        }
    }
}

// ---------------------------------------------------------------------------
// ONE fused kernel: 2048 blocks x 256 threads.
// ---------------------------------------------------------------------------
__global__ void __launch_bounds__(SIZE, 4)
fused_kernel(const float* __restrict__ t,
             const float* __restrict__ y,
             const float* __restrict__ K,
             const float* __restrict__ C,
             const float* __restrict__ M,
             float* __restrict__ out) {
    __shared__ float sm[SIZE];   // [u(128) | v(128)]
    int b   = blockIdx.x;
    int tid = threadIdx.x;

    // ---- Kick off the y row load early (independent of everything below) --
    float yv = y[b * SIZE + tid];

    // ---- Compute this thread's 4 float4 of its Jb segment -----------------
    int s = b & (SEGS - 1);
    int g = b >> 4;
    int segBase = s * SEG_F4;                  // float4 index within one copy

    float4 jr[4];
    #pragma unroll
    for (int q = 0; q < 4; q++) {
        int e = (segBase + q * 256 + tid) * 4; // linear float index in Jb
        int r = e >> 8;
        int c = e & (SIZE - 1);
        jr[q].x = jb_val(r, c + 0, K, C, M);
        jr[q].y = jb_val(r, c + 1, K, C, M);
        jr[q].z = jb_val(r, c + 2, K, C, M);
        jr[q].w = jb_val(r, c + 3, K, C, M);
    }

    // ---- J broadcast FIRST: start the dominant store stream immediately ---
    float4* __restrict__ j4 = reinterpret_cast<float4*>(out + YDOT_FLOATS);
    int c0 = g * CPB;
    #pragma unroll 4
    for (int k = 0; k < CPB; k++) {
        float4* dst = j4 + (long long)(c0 + k) * 16384 + segBase + tid;
        __stcs(dst + 0 * 256, jr[0]);
        __stcs(dst + 1 * 256, jr[1]);
        __stcs(dst + 2 * 256, jr[2]);
        __stcs(dst + 3 * 256, jr[3]);
    }

    // ---- ydot (y-load latency + compute hidden under store drain) ---------
    sm[tid] = yv;
    __syncthreads();

    float res;
    if (tid < HALF) {
        res = sm[HALF + tid];                  // ydot[:half] = v
    } else {
        int i = tid - HALF;
        float Mi = M[i] * M_SCALE;
        float acc = 0.0f;
        if (i < HALF - 1) {
            float f = K[i] * (sm[i + 1] - sm[i])
                    + (C[i] * C_SCALE) * (sm[HALF + i + 1] - sm[HALF + i]);
            acc += f / Mi;
        }
        if (i > 0) {
            float fm = K[i - 1] * (sm[i] - sm[i - 1])
                     + (C[i - 1] * C_SCALE) * (sm[HALF + i] - sm[HALF + i - 1]);
            acc -= fm / Mi;
        }
        if (i == HALF - 1) {
            acc -= (K[HALF - 1] * sm[HALF - 1]
                  + (C[HALF - 1] * C_SCALE) * sm[SIZE - 1]) / Mi;
        }
        if (i == 0) {
            acc += sinf(t[b]) / Mi;
        }
        res = acc;
    }
    out[b * SIZE + tid] = res;
}

// ---------------------------------------------------------------------------
extern "C" void kernel_launch(void* const* d_in, const int* in_sizes, int n_in,
                              void* d_out, int out_size) {
    const float* t = (const float*)d_in[0];
    const float* y = (const float*)d_in[1];
    const float* K = (const float*)d_in[2];
    const float* C = (const float*)d_in[3];
    const float* M = (const float*)d_in[4];
    float* out = (float*)d_out;

    fused_kernel<<<NBLK, SIZE>>>(t, y, K, C, M, out);
}

// round 15
// speedup vs baseline: 1.0104x; 1.0104x over previous
#include <cuda_runtime.h>
#include <math.h>

// Problem constants
#define NCHUNK 32
#define NBATCH 64
#define HALF   128
#define SIZE   (2 * HALF)            // 256
#define NROWS  (NCHUNK * NBATCH)     // 2048
#define C_SCALE 1e-4f
#define M_SCALE 1e-5f

#define YDOT_FLOATS (NROWS * SIZE)   // 524288

// FINAL (measured best): 16 segments x 128 groups = 2048 blocks.
// Each block holds one 16KB segment (4 float4/thread in registers) and
// writes it to 16 CONTIGUOUS batch copies with unroll-4 streaming STG.128.
// Pinned at the path-independent HBM write ceiling (~5.8 TB/s, verified
// against TMA bulk stores across 9 configurations); 539MB compulsory
// output => ~94% of the compulsory-traffic ideal.
#define SEGS 16
#define GRP  128
#define NBLK (SEGS * GRP)            // 2048
#define CPB  (NROWS / GRP)           // 16 copies per block
#define SEG_F4 1024                  // float4 per segment

// ---------------------------------------------------------------------------
// Closed-form Jb[r][c] (256x256)
// ---------------------------------------------------------------------------
__device__ __forceinline__ float jb_val(int r, int c,
                                        const float* __restrict__ K,
                                        const float* __restrict__ C,
                                        const float* __restrict__ M) {
    if (r < HALF) {
        return (c == r + HALF) ? 1.0f : 0.0f;
    }
    int i = r - HALF;
    int j = (c < HALF) ? c : (c - HALF);
    int d = j - i;
    if (d < -1 || d > 1) return 0.0f;

    float Mi = M[i] * M_SCALE;
    if (c < HALF) {
        if (d == 0) {
            float v = -K[i] / Mi;
            if (i > 0) v -= K[i - 1] / Mi;
            return v;
        } else if (d == 1) {
            return K[i] / Mi;
        } else {
            return K[i - 1] / Mi;
        }
    } else {
        if (d == 0) {
            float v = -(C[i] * C_SCALE) / Mi;
            if (i > 0) v -= (C[i - 1] * C_SCALE) / Mi;
            return v;
        } else if (d == 1) {
            return (C[i] * C_SCALE) / Mi;
        } else {
            return (C[i - 1] * C_SCALE) / Mi;
        }
    }
}

// ---------------------------------------------------------------------------
// ONE fused kernel: 2048 blocks x 256 threads.
// ---------------------------------------------------------------------------
__global__ void __launch_bounds__(SIZE, 4)
fused_kernel(const float* __restrict__ t,
             const float* __restrict__ y,
             const float* __restrict__ K,
             const float* __restrict__ C,
             const float* __restrict__ M,
             float* __restrict__ out) {
    __shared__ float sm[SIZE];   // [u(128) | v(128)]
    int b   = blockIdx.x;
    int tid = threadIdx.x;

    // ---- Part A: ydot for row b -------------------------------------------
    sm[tid] = y[b * SIZE + tid];

    // ---- Part B prologue: this thread's 4 float4 of its Jb segment --------
    int s = b & (SEGS - 1);
    int g = b >> 4;
    int segBase = s * SEG_F4;                  // float4 index within one copy

    float4 jr[4];
    #pragma unroll
    for (int q = 0; q < 4; q++) {
        int e = (segBase + q * 256 + tid) * 4; // linear float index in Jb
        int r = e >> 8;
        int c = e & (SIZE - 1);
        jr[q].x = jb_val(r, c + 0, K, C, M);
        jr[q].y = jb_val(r, c + 1, K, C, M);
        jr[q].z = jb_val(r, c + 2, K, C, M);
        jr[q].w = jb_val(r, c + 3, K, C, M);
    }

    __syncthreads();

    // ---- Part A compute + store -------------------------------------------
    float res;
    if (tid < HALF) {
        res = sm[HALF + tid];                  // ydot[:half] = v
    } else {
        int i = tid - HALF;
        float Mi = M[i] * M_SCALE;
        float acc = 0.0f;
        if (i < HALF - 1) {
            float f = K[i] * (sm[i + 1] - sm[i])
                    + (C[i] * C_SCALE) * (sm[HALF + i + 1] - sm[HALF + i]);
            acc += f / Mi;
        }
        if (i > 0) {
            float fm = K[i - 1] * (sm[i] - sm[i - 1])
                     + (C[i - 1] * C_SCALE) * (sm[HALF + i] - sm[HALF + i - 1]);
            acc -= fm / Mi;
        }
        if (i == HALF - 1) {
            acc -= (K[HALF - 1] * sm[HALF - 1]
                  + (C[HALF - 1] * C_SCALE) * sm[SIZE - 1]) / Mi;
        }
        if (i == 0) {
            acc += sinf(t[b]) / Mi;
        }
        res = acc;
    }
    out[b * SIZE + tid] = res;

    // ---- Part B: broadcast J (register replay, streaming STG.128) ---------
    float4* __restrict__ j4 = reinterpret_cast<float4*>(out + YDOT_FLOATS);
    int c0 = g * CPB;
    #pragma unroll 4
    for (int k = 0; k < CPB; k++) {
        float4* dst = j4 + (long long)(c0 + k) * 16384 + segBase + tid;
        __stcs(dst + 0 * 256, jr[0]);
        __stcs(dst + 1 * 256, jr[1]);
        __stcs(dst + 2 * 256, jr[2]);
        __stcs(dst + 3 * 256, jr[3]);
    }
}

// ---------------------------------------------------------------------------
extern "C" void kernel_launch(void* const* d_in, const int* in_sizes, int n_in,
                              void* d_out, int out_size) {
    const float* t = (const float*)d_in[0];
    const float* y = (const float*)d_in[1];
    const float* K = (const float*)d_in[2];
    const float* C = (const float*)d_in[3];
    const float* M = (const float*)d_in[4];
    float* out = (float*)d_out;

    fused_kernel<<<NBLK, SIZE>>>(t, y, K, C, M, out);
}